// round 12
// baseline (speedup 1.0000x reference)
#include <cuda_runtime.h>

// DynamicMaskHead fused kernel, round 12:
//  = round-11 (the allocation-clean 61.5us platform) + ONE change:
//    register-free software prefetch of the NEXT unit's 8 feat cache lines
//    via prefetch.global.L1 (no dest register, no scoreboard, address temps
//    dead immediately -> cannot perturb the proven register allocation).
//  Everything else is byte-identical to round 11:
//    * phase-1 indices derived per-iteration by DIVISION (no carried state)
//    * c-outer layers, one f32x2 accumulator pair live
//    * 8x LDG.128 feats at loop top, duplicated weights in smem
//    * __launch_bounds__(128,4)

#define WW    192
#define HH    128
#define HWSZ  (192*128)
#define CIN   8
#define TH    16
#define NROWS (TH + 1)           // +1 halo row above
#define UPR   (WW/4)             // 48 four-pixel units per row
#define NUNIT (NROWS * UPR)      // 816
#define OWW   384
#define OHH   256
#define NP    169

__device__ __forceinline__ float2 ffma2(float2 a, float2 b, float2 c) {
    float2 d;
    asm("fma.rn.f32x2 %0, %1, %2, %3;"
        : "=l"(reinterpret_cast<unsigned long long&>(d))
        : "l"(reinterpret_cast<unsigned long long&>(a)),
          "l"(reinterpret_cast<unsigned long long&>(b)),
          "l"(reinterpret_cast<unsigned long long&>(c)));
    return d;
}
__device__ __forceinline__ float2 relu2(float2 v) {
    return make_float2(fmaxf(v.x, 0.f), fmaxf(v.y, 0.f));
}
__device__ __forceinline__ float2 f2(float a, float b) { return make_float2(a, b); }

__global__ __launch_bounds__(128, 4) void dyn_mask_head_kernel(
    const float* __restrict__ mask_feats,   // [2, 8, 128, 192]
    const float* __restrict__ params,       // [n_inst, 169]
    const float* __restrict__ locs,         // [n_inst, 2] (x, y)
    const float* __restrict__ soi,          // [5]
    const int*   __restrict__ im_inds,      // [n_inst]
    const int*   __restrict__ fpn_levels,   // [n_inst]
    float*       __restrict__ out)          // [n_inst, 1, 256, 384]
{
    const int n   = blockIdx.y;
    const int r0  = blockIdx.x * TH;
    const int tid = threadIdx.x;

    __shared__ __align__(16) float sw1[8][20]; // w0..w7 dup(16) + bias dup(2) + pad
    __shared__ __align__(16) float sw2[20];    // w dup(16) + bias dup(2) + pad
    __shared__ __align__(16) float sL[NROWS][WW];
    __shared__ __align__(16) float sw0[8][24]; // w0..w9 dup(20) + bias dup(2) + pad

    {
        const float* p = params + n * NP;
        for (int t = tid; t < NP; t += 128) {
            float v = __ldg(p + t);
            if (t < 80) {
                int c = t / 10, j = t - 10 * c;
                sw0[c][2*j] = v; sw0[c][2*j+1] = v;
            } else if (t < 144) {
                int q = t - 80; int c = q >> 3, j = q & 7;
                sw1[c][2*j] = v; sw1[c][2*j+1] = v;
            } else if (t < 152) {
                int j = t - 144;
                sw2[2*j] = v; sw2[2*j+1] = v;
            } else if (t < 160) {
                int c = t - 152;
                sw0[c][20] = v; sw0[c][21] = v;
            } else if (t < 168) {
                int c = t - 160;
                sw1[c][16] = v; sw1[c][17] = v;
            } else {
                sw2[16] = v; sw2[17] = v;
            }
        }
    }
    __syncthreads();

    const int   im  = im_inds[n];
    const float inv = 1.0f / soi[fpn_levels[n]];
    const float lx  = locs[2*n + 0];
    const float ly  = locs[2*n + 1];
    const float* fb = mask_feats + (size_t)im * (CIN * HWSZ);
    const float s8  = 8.0f * inv;

    // ---- phase 1: logits, 4 consecutive pixels per thread per iter ----
    // R3-form indexing: i derived fresh each iteration, rl/m by division
    // (dead after address computation -> allocation-clean).
#pragma unroll 1
    for (int it = 0; it < 7; it++) {
        const int i = tid + it * 128;
        if (i >= NUNIT) break;
        const int rl = i / UPR;
        const int m  = i - rl * UPR;
        const int x0 = 4 * m;
        const int rc = max(r0 - 1 + rl, 0);

        const float* fp = fb + rc * WW + x0;
        float4 f[8];
#pragma unroll
        for (int k = 0; k < 8; k++)
            f[k] = *reinterpret_cast<const float4*>(fp + k * HWSZ);

        // register-free prefetch of NEXT unit's feat lines into L1.
        // No dest reg, no scoreboard; all temps dead before layer 0.
        {
            const int i2 = i + 128;
            if (i2 < NUNIT) {
                const int rl2 = i2 / UPR;
                const int m2  = i2 - rl2 * UPR;
                const int rc2 = max(r0 - 1 + rl2, 0);
                const float* fq = fb + rc2 * WW + 4 * m2;
#pragma unroll
                for (int k = 0; k < 8; k++)
                    asm volatile("prefetch.global.L1 [%0];" :: "l"(fq + k * HWSZ));
            }
        }

        const float ryv = (ly - (float)(rc * 8 + 4)) * inv;
        const float2 ryd = f2(ryv, ryv);
        const float rxv = (lx - (float)(x0 * 8 + 4)) * inv;
        const float2 rxA = f2(rxv, rxv - s8);
        const float2 rxB = f2(rxv - 2.f * s8, rxv - 3.f * s8);

        // ---- layer 0: 10 -> 8, relu. c-outer (one acc pair live) ----
        float2 hA[8], hB[8];
#pragma unroll
        for (int c = 0; c < 8; c++) {
            const float4* wc = reinterpret_cast<const float4*>(sw0[c]);
            const float2 bd = *reinterpret_cast<const float2*>(&sw0[c][20]);
            float4 w01 = wc[0];
            float2 aA = ffma2(f2(w01.x, w01.y), rxA, bd);
            float2 aB = ffma2(f2(w01.x, w01.y), rxB, bd);
            aA = ffma2(f2(w01.z, w01.w), ryd, aA);
            aB = ffma2(f2(w01.z, w01.w), ryd, aB);
#pragma unroll
            for (int kk = 0; kk < 4; kk++) {     // feats k = 2kk, 2kk+1
                float4 wp = wc[1 + kk];
                aA = ffma2(f2(wp.x, wp.y), f2(f[2*kk].x,   f[2*kk].y),   aA);
                aB = ffma2(f2(wp.x, wp.y), f2(f[2*kk].z,   f[2*kk].w),   aB);
                aA = ffma2(f2(wp.z, wp.w), f2(f[2*kk+1].x, f[2*kk+1].y), aA);
                aB = ffma2(f2(wp.z, wp.w), f2(f[2*kk+1].z, f[2*kk+1].w), aB);
            }
            hA[c] = relu2(aA);
            hB[c] = relu2(aB);
        }

        // ---- layer 1: 8 -> 8, relu ----
        float2 gA[8], gB[8];
#pragma unroll
        for (int c = 0; c < 8; c++) {
            const float4* wc = reinterpret_cast<const float4*>(sw1[c]);
            const float2 bd = *reinterpret_cast<const float2*>(&sw1[c][16]);
            float2 aA = bd, aB = bd;
#pragma unroll
            for (int kk = 0; kk < 4; kk++) {
                float4 wp = wc[kk];
                aA = ffma2(f2(wp.x, wp.y), hA[2*kk],   aA);
                aB = ffma2(f2(wp.x, wp.y), hB[2*kk],   aB);
                aA = ffma2(f2(wp.z, wp.w), hA[2*kk+1], aA);
                aB = ffma2(f2(wp.z, wp.w), hB[2*kk+1], aB);
            }
            gA[c] = relu2(aA);
            gB[c] = relu2(aB);
        }

        // ---- layer 2: 8 -> 1 ----
        {
            const float4* wc = reinterpret_cast<const float4*>(sw2);
            const float2 bd = *reinterpret_cast<const float2*>(&sw2[16]);
            float2 oA = bd, oB = bd;
#pragma unroll
            for (int kk = 0; kk < 4; kk++) {
                float4 wp = wc[kk];
                oA = ffma2(f2(wp.x, wp.y), gA[2*kk],   oA);
                oB = ffma2(f2(wp.x, wp.y), gB[2*kk],   oB);
                oA = ffma2(f2(wp.z, wp.w), gA[2*kk+1], oA);
                oB = ffma2(f2(wp.z, wp.w), gB[2*kk+1], oB);
            }
            float4 v = make_float4(oA.x, oA.y, oB.x, oB.y);
            *reinterpret_cast<float4*>(&sL[rl][x0]) = v;
        }
    }
    __syncthreads();

    // ---- phase 2: aligned_bilinear x2 from smem tile, float4 stores ----
    // out[o] = interp[max(o-1,0)]; interp[j] even -> t[j/2],
    //                               odd  -> 0.5*(t[j>>1] + t[(j>>1)+1])
    float* ob = out + (size_t)n * (OHH * OWW) + (size_t)(2 * r0) * OWW;
    const int NG = 32 * (WW / 2);  // 32 output rows x 96 groups of 4 cols
    for (int g = tid; g < NG; g += 128) {
        const int oyl = g / 96;
        const int m   = g - oyl * 96;
        const int oy  = 2 * r0 + oyl;
        const int iy  = max(oy - 1, 0);
        const int ra  = (iy >> 1) - r0 + 1;   // smem slot of row (iy>>1)

        const int cA = max(2 * m - 1, 0);
        const int cB = 2 * m;
        const int cC = 2 * m + 1;

        float va, vb, vc;
        if (iy & 1) {
            va = 0.5f * (sL[ra][cA] + sL[ra + 1][cA]);
            vb = 0.5f * (sL[ra][cB] + sL[ra + 1][cB]);
            vc = 0.5f * (sL[ra][cC] + sL[ra + 1][cC]);
        } else {
            va = sL[ra][cA];
            vb = sL[ra][cB];
            vc = sL[ra][cC];
        }
        float4 o;
        o.x = 0.5f * (va + vb);   // even ox (left-edge clamp folds in at m==0)
        o.y = vb;                 // odd ox
        o.z = 0.5f * (vb + vc);
        o.w = vc;
        *reinterpret_cast<float4*>(ob + oyl * OWW + 4 * m) = o;
    }
}

extern "C" void kernel_launch(void* const* d_in, const int* in_sizes, int n_in,
                              void* d_out, int out_size) {
    const float* mask_feats = (const float*)d_in[0];
    const float* params     = (const float*)d_in[1];
    const float* locs       = (const float*)d_in[2];
    const float* soi        = (const float*)d_in[3];
    const int*   im_inds    = (const int*)d_in[4];
    const int*   fpn_levels = (const int*)d_in[5];
    float*       out        = (float*)d_out;

    const int n_inst = in_sizes[4];          // 256
    dim3 grid(HH / TH, n_inst);
    dyn_mask_head_kernel<<<grid, 128>>>(mask_feats, params, locs, soi,
                                        im_inds, fpn_levels, out);
}

// round 13
// speedup vs baseline: 1.0681x; 1.0681x over previous
#include <cuda_runtime.h>

// DynamicMaskHead fused kernel, round 13:
//  = round-11's allocation-clean hot-loop form, with two changes only:
//    (1) TH=32 row tiles (33-row halo): -3% phase-1 math, half the blocks
//        -> half the param staging / __syncthreads / launch fixed cost
//    (2) the R12 prefetch removed (measured neutral-to-negative)
//  Everything else identical:
//    * phase-1 indices derived per-iteration by DIVISION (no carried state)
//    * c-outer layers, one f32x2 accumulator pair live
//    * 8x LDG.128 feats at loop top, duplicated weights in smem (LDS.128 =
//      two ready [w,w] splats, warp-uniform broadcast)
//    * __launch_bounds__(128,4)

#define WW    192
#define HH    128
#define HWSZ  (192*128)
#define CIN   8
#define TH    32
#define NROWS (TH + 1)           // 33 (+1 halo row above)
#define UPR   (WW/4)             // 48 four-pixel units per row
#define NUNIT (NROWS * UPR)      // 1584
#define OWW   384
#define OHH   256
#define NP    169

__device__ __forceinline__ float2 ffma2(float2 a, float2 b, float2 c) {
    float2 d;
    asm("fma.rn.f32x2 %0, %1, %2, %3;"
        : "=l"(reinterpret_cast<unsigned long long&>(d))
        : "l"(reinterpret_cast<unsigned long long&>(a)),
          "l"(reinterpret_cast<unsigned long long&>(b)),
          "l"(reinterpret_cast<unsigned long long&>(c)));
    return d;
}
__device__ __forceinline__ float2 relu2(float2 v) {
    return make_float2(fmaxf(v.x, 0.f), fmaxf(v.y, 0.f));
}
__device__ __forceinline__ float2 f2(float a, float b) { return make_float2(a, b); }

__global__ __launch_bounds__(128, 4) void dyn_mask_head_kernel(
    const float* __restrict__ mask_feats,   // [2, 8, 128, 192]
    const float* __restrict__ params,       // [n_inst, 169]
    const float* __restrict__ locs,         // [n_inst, 2] (x, y)
    const float* __restrict__ soi,          // [5]
    const int*   __restrict__ im_inds,      // [n_inst]
    const int*   __restrict__ fpn_levels,   // [n_inst]
    float*       __restrict__ out)          // [n_inst, 1, 256, 384]
{
    const int n   = blockIdx.y;
    const int r0  = blockIdx.x * TH;
    const int tid = threadIdx.x;

    __shared__ __align__(16) float sw1[8][20]; // w0..w7 dup(16) + bias dup(2) + pad
    __shared__ __align__(16) float sw2[20];    // w dup(16) + bias dup(2) + pad
    __shared__ __align__(16) float sL[NROWS][WW];
    __shared__ __align__(16) float sw0[8][24]; // w0..w9 dup(20) + bias dup(2) + pad

    {
        const float* p = params + n * NP;
        for (int t = tid; t < NP; t += 128) {
            float v = __ldg(p + t);
            if (t < 80) {
                int c = t / 10, j = t - 10 * c;
                sw0[c][2*j] = v; sw0[c][2*j+1] = v;
            } else if (t < 144) {
                int q = t - 80; int c = q >> 3, j = q & 7;
                sw1[c][2*j] = v; sw1[c][2*j+1] = v;
            } else if (t < 152) {
                int j = t - 144;
                sw2[2*j] = v; sw2[2*j+1] = v;
            } else if (t < 160) {
                int c = t - 152;
                sw0[c][20] = v; sw0[c][21] = v;
            } else if (t < 168) {
                int c = t - 160;
                sw1[c][16] = v; sw1[c][17] = v;
            } else {
                sw2[16] = v; sw2[17] = v;
            }
        }
    }
    __syncthreads();

    const int   im  = im_inds[n];
    const float inv = 1.0f / soi[fpn_levels[n]];
    const float lx  = locs[2*n + 0];
    const float ly  = locs[2*n + 1];
    const float* fb = mask_feats + (size_t)im * (CIN * HWSZ);
    const float s8  = 8.0f * inv;

    // ---- phase 1: logits, 4 consecutive pixels per thread per iter ----
    // R11-form indexing: i derived fresh each iteration, rl/m by division
    // (dead after address computation -> allocation-clean).
#pragma unroll 1
    for (int it = 0; it < 13; it++) {
        const int i = tid + it * 128;
        if (i >= NUNIT) break;
        const int rl = i / UPR;
        const int m  = i - rl * UPR;
        const int x0 = 4 * m;
        const int rc = max(r0 - 1 + rl, 0);

        const float* fp = fb + rc * WW + x0;
        float4 f[8];
#pragma unroll
        for (int k = 0; k < 8; k++)
            f[k] = *reinterpret_cast<const float4*>(fp + k * HWSZ);

        const float ryv = (ly - (float)(rc * 8 + 4)) * inv;
        const float2 ryd = f2(ryv, ryv);
        const float rxv = (lx - (float)(x0 * 8 + 4)) * inv;
        const float2 rxA = f2(rxv, rxv - s8);
        const float2 rxB = f2(rxv - 2.f * s8, rxv - 3.f * s8);

        // ---- layer 0: 10 -> 8, relu. c-outer (one acc pair live) ----
        float2 hA[8], hB[8];
#pragma unroll
        for (int c = 0; c < 8; c++) {
            const float4* wc = reinterpret_cast<const float4*>(sw0[c]);
            const float2 bd = *reinterpret_cast<const float2*>(&sw0[c][20]);
            float4 w01 = wc[0];
            float2 aA = ffma2(f2(w01.x, w01.y), rxA, bd);
            float2 aB = ffma2(f2(w01.x, w01.y), rxB, bd);
            aA = ffma2(f2(w01.z, w01.w), ryd, aA);
            aB = ffma2(f2(w01.z, w01.w), ryd, aB);
#pragma unroll
            for (int kk = 0; kk < 4; kk++) {     // feats k = 2kk, 2kk+1
                float4 wp = wc[1 + kk];
                aA = ffma2(f2(wp.x, wp.y), f2(f[2*kk].x,   f[2*kk].y),   aA);
                aB = ffma2(f2(wp.x, wp.y), f2(f[2*kk].z,   f[2*kk].w),   aB);
                aA = ffma2(f2(wp.z, wp.w), f2(f[2*kk+1].x, f[2*kk+1].y), aA);
                aB = ffma2(f2(wp.z, wp.w), f2(f[2*kk+1].z, f[2*kk+1].w), aB);
            }
            hA[c] = relu2(aA);
            hB[c] = relu2(aB);
        }

        // ---- layer 1: 8 -> 8, relu ----
        float2 gA[8], gB[8];
#pragma unroll
        for (int c = 0; c < 8; c++) {
            const float4* wc = reinterpret_cast<const float4*>(sw1[c]);
            const float2 bd = *reinterpret_cast<const float2*>(&sw1[c][16]);
            float2 aA = bd, aB = bd;
#pragma unroll
            for (int kk = 0; kk < 4; kk++) {
                float4 wp = wc[kk];
                aA = ffma2(f2(wp.x, wp.y), hA[2*kk],   aA);
                aB = ffma2(f2(wp.x, wp.y), hB[2*kk],   aB);
                aA = ffma2(f2(wp.z, wp.w), hA[2*kk+1], aA);
                aB = ffma2(f2(wp.z, wp.w), hB[2*kk+1], aB);
            }
            gA[c] = relu2(aA);
            gB[c] = relu2(aB);
        }

        // ---- layer 2: 8 -> 1 ----
        {
            const float4* wc = reinterpret_cast<const float4*>(sw2);
            const float2 bd = *reinterpret_cast<const float2*>(&sw2[16]);
            float2 oA = bd, oB = bd;
#pragma unroll
            for (int kk = 0; kk < 4; kk++) {
                float4 wp = wc[kk];
                oA = ffma2(f2(wp.x, wp.y), gA[2*kk],   oA);
                oB = ffma2(f2(wp.x, wp.y), gB[2*kk],   oB);
                oA = ffma2(f2(wp.z, wp.w), gA[2*kk+1], oA);
                oB = ffma2(f2(wp.z, wp.w), gB[2*kk+1], oB);
            }
            float4 v = make_float4(oA.x, oA.y, oB.x, oB.y);
            *reinterpret_cast<float4*>(&sL[rl][x0]) = v;
        }
    }
    __syncthreads();

    // ---- phase 2: aligned_bilinear x2 from smem tile, float4 stores ----
    // out[o] = interp[max(o-1,0)]; interp[j] even -> t[j/2],
    //                               odd  -> 0.5*(t[j>>1] + t[(j>>1)+1])
    float* ob = out + (size_t)n * (OHH * OWW) + (size_t)(2 * r0) * OWW;
    const int NG = (2 * TH) * (WW / 2);  // 64 output rows x 96 groups of 4 cols
    for (int g = tid; g < NG; g += 128) {
        const int oyl = g / 96;
        const int m   = g - oyl * 96;
        const int oy  = 2 * r0 + oyl;
        const int iy  = max(oy - 1, 0);
        const int ra  = (iy >> 1) - r0 + 1;   // smem slot of row (iy>>1)

        const int cA = max(2 * m - 1, 0);
        const int cB = 2 * m;
        const int cC = 2 * m + 1;

        float va, vb, vc;
        if (iy & 1) {
            va = 0.5f * (sL[ra][cA] + sL[ra + 1][cA]);
            vb = 0.5f * (sL[ra][cB] + sL[ra + 1][cB]);
            vc = 0.5f * (sL[ra][cC] + sL[ra + 1][cC]);
        } else {
            va = sL[ra][cA];
            vb = sL[ra][cB];
            vc = sL[ra][cC];
        }
        float4 o;
        o.x = 0.5f * (va + vb);   // even ox (left-edge clamp folds in at m==0)
        o.y = vb;                 // odd ox
        o.z = 0.5f * (vb + vc);
        o.w = vc;
        *reinterpret_cast<float4*>(ob + oyl * OWW + 4 * m) = o;
    }
}

extern "C" void kernel_launch(void* const* d_in, const int* in_sizes, int n_in,
                              void* d_out, int out_size) {
    const float* mask_feats = (const float*)d_in[0];
    const float* params     = (const float*)d_in[1];
    const float* locs       = (const float*)d_in[2];
    const float* soi        = (const float*)d_in[3];
    const int*   im_inds    = (const int*)d_in[4];
    const int*   fpn_levels = (const int*)d_in[5];
    float*       out        = (float*)d_out;

    const int n_inst = in_sizes[4];          // 256
    dim3 grid(HH / TH, n_inst);               // (4, 256)
    dyn_mask_head_kernel<<<grid, 128>>>(mask_feats, params, locs, soi,
                                        im_inds, fpn_levels, out);
}

// round 15
// speedup vs baseline: 1.0860x; 1.0168x over previous
#include <cuda_runtime.h>

// DynamicMaskHead fused kernel, round 15:
//  = round-13 (TH=32, allocation-clean division-indexed hot loop, 60.2us)
//  + phase-2 upsample widened to 8 output cols/thread (one LDS.128 + one
//    halo scalar per row instead of 3-6 scalar LDS; iterations halved).
//  relu stays scalar fmaxf (R14 showed max.f32x2 does not exist in PTX).
//  Hot-loop form unchanged: division-derived per-iteration indices, c-outer
//  layers, 8x LDG.128 feats at loop top, duplicated weights in smem,
//  __launch_bounds__(128,4).

#define WW    192
#define HH    128
#define HWSZ  (192*128)
#define CIN   8
#define TH    32
#define NROWS (TH + 1)           // 33 (+1 halo row above)
#define UPR   (WW/4)             // 48 four-pixel units per row
#define NUNIT (NROWS * UPR)      // 1584
#define OWW   384
#define OHH   256
#define NP    169

__device__ __forceinline__ float2 ffma2(float2 a, float2 b, float2 c) {
    float2 d;
    asm("fma.rn.f32x2 %0, %1, %2, %3;"
        : "=l"(reinterpret_cast<unsigned long long&>(d))
        : "l"(reinterpret_cast<unsigned long long&>(a)),
          "l"(reinterpret_cast<unsigned long long&>(b)),
          "l"(reinterpret_cast<unsigned long long&>(c)));
    return d;
}
__device__ __forceinline__ float2 relu2(float2 v) {
    return make_float2(fmaxf(v.x, 0.f), fmaxf(v.y, 0.f));
}
__device__ __forceinline__ float2 f2(float a, float b) { return make_float2(a, b); }

__global__ __launch_bounds__(128, 4) void dyn_mask_head_kernel(
    const float* __restrict__ mask_feats,   // [2, 8, 128, 192]
    const float* __restrict__ params,       // [n_inst, 169]
    const float* __restrict__ locs,         // [n_inst, 2] (x, y)
    const float* __restrict__ soi,          // [5]
    const int*   __restrict__ im_inds,      // [n_inst]
    const int*   __restrict__ fpn_levels,   // [n_inst]
    float*       __restrict__ out)          // [n_inst, 1, 256, 384]
{
    const int n   = blockIdx.y;
    const int r0  = blockIdx.x * TH;
    const int tid = threadIdx.x;

    __shared__ __align__(16) float sw1[8][20]; // w0..w7 dup(16) + bias dup(2) + pad
    __shared__ __align__(16) float sw2[20];    // w dup(16) + bias dup(2) + pad
    __shared__ __align__(16) float sL[NROWS][WW];
    __shared__ __align__(16) float sw0[8][24]; // w0..w9 dup(20) + bias dup(2) + pad

    {
        const float* p = params + n * NP;
        for (int t = tid; t < NP; t += 128) {
            float v = __ldg(p + t);
            if (t < 80) {
                int c = t / 10, j = t - 10 * c;
                sw0[c][2*j] = v; sw0[c][2*j+1] = v;
            } else if (t < 144) {
                int q = t - 80; int c = q >> 3, j = q & 7;
                sw1[c][2*j] = v; sw1[c][2*j+1] = v;
            } else if (t < 152) {
                int j = t - 144;
                sw2[2*j] = v; sw2[2*j+1] = v;
            } else if (t < 160) {
                int c = t - 152;
                sw0[c][20] = v; sw0[c][21] = v;
            } else if (t < 168) {
                int c = t - 160;
                sw1[c][16] = v; sw1[c][17] = v;
            } else {
                sw2[16] = v; sw2[17] = v;
            }
        }
    }
    __syncthreads();

    const int   im  = im_inds[n];
    const float inv = 1.0f / soi[fpn_levels[n]];
    const float lx  = locs[2*n + 0];
    const float ly  = locs[2*n + 1];
    const float* fb = mask_feats + (size_t)im * (CIN * HWSZ);
    const float s8  = 8.0f * inv;

    // ---- phase 1: logits, 4 consecutive pixels per thread per iter ----
#pragma unroll 1
    for (int it = 0; it < 13; it++) {
        const int i = tid + it * 128;
        if (i >= NUNIT) break;
        const int rl = i / UPR;
        const int m  = i - rl * UPR;
        const int x0 = 4 * m;
        const int rc = max(r0 - 1 + rl, 0);

        const float* fp = fb + rc * WW + x0;
        float4 f[8];
#pragma unroll
        for (int k = 0; k < 8; k++)
            f[k] = *reinterpret_cast<const float4*>(fp + k * HWSZ);

        const float ryv = (ly - (float)(rc * 8 + 4)) * inv;
        const float2 ryd = f2(ryv, ryv);
        const float rxv = (lx - (float)(x0 * 8 + 4)) * inv;
        const float2 rxA = f2(rxv, rxv - s8);
        const float2 rxB = f2(rxv - 2.f * s8, rxv - 3.f * s8);

        // ---- layer 0: 10 -> 8, relu. c-outer (one acc pair live) ----
        float2 hA[8], hB[8];
#pragma unroll
        for (int c = 0; c < 8; c++) {
            const float4* wc = reinterpret_cast<const float4*>(sw0[c]);
            const float2 bd = *reinterpret_cast<const float2*>(&sw0[c][20]);
            float4 w01 = wc[0];
            float2 aA = ffma2(f2(w01.x, w01.y), rxA, bd);
            float2 aB = ffma2(f2(w01.x, w01.y), rxB, bd);
            aA = ffma2(f2(w01.z, w01.w), ryd, aA);
            aB = ffma2(f2(w01.z, w01.w), ryd, aB);
#pragma unroll
            for (int kk = 0; kk < 4; kk++) {     // feats k = 2kk, 2kk+1
                float4 wp = wc[1 + kk];
                aA = ffma2(f2(wp.x, wp.y), f2(f[2*kk].x,   f[2*kk].y),   aA);
                aB = ffma2(f2(wp.x, wp.y), f2(f[2*kk].z,   f[2*kk].w),   aB);
                aA = ffma2(f2(wp.z, wp.w), f2(f[2*kk+1].x, f[2*kk+1].y), aA);
                aB = ffma2(f2(wp.z, wp.w), f2(f[2*kk+1].z, f[2*kk+1].w), aB);
            }
            hA[c] = relu2(aA);
            hB[c] = relu2(aB);
        }

        // ---- layer 1: 8 -> 8, relu ----
        float2 gA[8], gB[8];
#pragma unroll
        for (int c = 0; c < 8; c++) {
            const float4* wc = reinterpret_cast<const float4*>(sw1[c]);
            const float2 bd = *reinterpret_cast<const float2*>(&sw1[c][16]);
            float2 aA = bd, aB = bd;
#pragma unroll
            for (int kk = 0; kk < 4; kk++) {
                float4 wp = wc[kk];
                aA = ffma2(f2(wp.x, wp.y), hA[2*kk],   aA);
                aB = ffma2(f2(wp.x, wp.y), hB[2*kk],   aB);
                aA = ffma2(f2(wp.z, wp.w), hA[2*kk+1], aA);
                aB = ffma2(f2(wp.z, wp.w), hB[2*kk+1], aB);
            }
            gA[c] = relu2(aA);
            gB[c] = relu2(aB);
        }

        // ---- layer 2: 8 -> 1 ----
        {
            const float4* wc = reinterpret_cast<const float4*>(sw2);
            const float2 bd = *reinterpret_cast<const float2*>(&sw2[16]);
            float2 oA = bd, oB = bd;
#pragma unroll
            for (int kk = 0; kk < 4; kk++) {
                float4 wp = wc[kk];
                oA = ffma2(f2(wp.x, wp.y), gA[2*kk],   oA);
                oB = ffma2(f2(wp.x, wp.y), gB[2*kk],   oB);
                oA = ffma2(f2(wp.z, wp.w), gA[2*kk+1], oA);
                oB = ffma2(f2(wp.z, wp.w), gB[2*kk+1], oB);
            }
            float4 v = make_float4(oA.x, oA.y, oB.x, oB.y);
            *reinterpret_cast<float4*>(&sL[rl][x0]) = v;
        }
    }
    __syncthreads();

    // ---- phase 2: aligned_bilinear x2, 8 output cols per thread per iter ----
    // out[o] = interp[max(o-1,0)]; interp[j] even -> t[j/2],
    //                               odd  -> 0.5*(t[j>>1] + t[(j>>1)+1])
    // For out cols 8q..8q+7 we need t[4q-1..4q+3]: one LDS.128 + halo scalar.
    float* ob = out + (size_t)n * (OHH * OWW) + (size_t)(2 * r0) * OWW;
    const int NG = (2 * TH) * (OWW / 8);   // 64 rows x 48 groups = 3072
    for (int g = tid; g < NG; g += 128) {
        const int oyl = g / 48;
        const int q   = g - oyl * 48;
        const int oy  = 2 * r0 + oyl;
        const int iy  = max(oy - 1, 0);
        const int ra  = (iy >> 1) - r0 + 1;   // smem slot of row (iy>>1)
        const int c0  = 4 * q;

        float4 v; float vm1;
        if (iy & 1) {
            const float4 a = *reinterpret_cast<const float4*>(&sL[ra][c0]);
            const float4 b = *reinterpret_cast<const float4*>(&sL[ra + 1][c0]);
            v.x = 0.5f * (a.x + b.x);
            v.y = 0.5f * (a.y + b.y);
            v.z = 0.5f * (a.z + b.z);
            v.w = 0.5f * (a.w + b.w);
            vm1 = (q > 0) ? 0.5f * (sL[ra][c0 - 1] + sL[ra + 1][c0 - 1]) : v.x;
        } else {
            v   = *reinterpret_cast<const float4*>(&sL[ra][c0]);
            vm1 = (q > 0) ? sL[ra][c0 - 1] : v.x;
        }

        float4 o1, o2;
        o1.x = 0.5f * (vm1 + v.x);   // out col 8q   (q==0: vm1=v.x -> v.x)
        o1.y = v.x;                  // 8q+1
        o1.z = 0.5f * (v.x + v.y);   // 8q+2
        o1.w = v.y;                  // 8q+3
        o2.x = 0.5f * (v.y + v.z);   // 8q+4
        o2.y = v.z;                  // 8q+5
        o2.z = 0.5f * (v.z + v.w);   // 8q+6
        o2.w = v.w;                  // 8q+7
        float* po = ob + oyl * OWW + 8 * q;
        *reinterpret_cast<float4*>(po)     = o1;
        *reinterpret_cast<float4*>(po + 4) = o2;
    }
}

extern "C" void kernel_launch(void* const* d_in, const int* in_sizes, int n_in,
                              void* d_out, int out_size) {
    const float* mask_feats = (const float*)d_in[0];
    const float* params     = (const float*)d_in[1];
    const float* locs       = (const float*)d_in[2];
    const float* soi        = (const float*)d_in[3];
    const int*   im_inds    = (const int*)d_in[4];
    const int*   fpn_levels = (const int*)d_in[5];
    float*       out        = (float*)d_out;

    const int n_inst = in_sizes[4];          // 256
    dim3 grid(HH / TH, n_inst);               // (4, 256)
    dyn_mask_head_kernel<<<grid, 128>>>(mask_feats, params, locs, soi,
                                        im_inds, fpn_levels, out);
}